// round 15
// baseline (speedup 1.0000x reference)
#include <cuda_runtime.h>
#include <cuda_fp16.h>
#include <math.h>
#include <stdint.h>

#define NB   8192
#define NA   32
#define NOBS 128
#define NH1  128
#define NHX  64
#define NACT 16

#define ROWB   272          // fp16 padded row (136 halfs); ldsm conflict-free
#define SPLIT_E 48          // tensor tiles (128 rows each); scalar tiles cover the rest
#define PAD    65           // fp32 scalar-path padded row

// ---------------------------------------------------------------------------
// Scratch + prepped weight images (allocation-free rule: __device__ globals)
// ---------------------------------------------------------------------------
__device__ unsigned int g_h2[NB * NA * 32];      // h  activations, half2-packed
__device__ unsigned int g_c2[NB * NA * 32];      // comm, half2-packed
__device__ unsigned int g_m16[2 * 32 * 16];      // M hi|lo fp16 images
// Transposed fp16 weight images, pad-136 rows: image[n][k] = W[k][n]
__device__ unsigned char g_W1t[NA * NH1 * ROWB];
__device__ unsigned char g_W2t[NA * NHX * ROWB];
__device__ unsigned char g_Wct[NA * NHX * ROWB];
__device__ unsigned char g_Wdt[NA * NACT * ROWB];

// ---------------------------------------------------------------------------
// Helpers
// ---------------------------------------------------------------------------
__device__ __forceinline__ uint32_t smem_u32(const void* p) {
    uint32_t a;
    asm("{ .reg .u64 t; cvta.to.shared.u64 t, %1; cvt.u32.u64 %0, t; }"
        : "=r"(a) : "l"(p));
    return a;
}
__device__ __forceinline__ void sts_u32(uint32_t addr, uint32_t v) {
    asm volatile("st.shared.b32 [%0], %1;" :: "r"(addr), "r"(v));
}
__device__ __forceinline__ void sts_v2(uint32_t addr, uint32_t a, uint32_t b) {
    asm volatile("st.shared.v2.b32 [%0], {%1,%2};" :: "r"(addr), "r"(a), "r"(b));
}
__device__ __forceinline__ void ldsm_x4(uint32_t &r0, uint32_t &r1, uint32_t &r2,
                                        uint32_t &r3, uint32_t addr) {
    asm volatile("ldmatrix.sync.aligned.m8n8.x4.shared.b16 {%0,%1,%2,%3}, [%4];"
                 : "=r"(r0), "=r"(r1), "=r"(r2), "=r"(r3) : "r"(addr));
}
__device__ __forceinline__ void ldsm_x4_t(uint32_t &r0, uint32_t &r1, uint32_t &r2,
                                          uint32_t &r3, uint32_t addr) {
    asm volatile("ldmatrix.sync.aligned.m8n8.x4.trans.shared.b16 {%0,%1,%2,%3}, [%4];"
                 : "=r"(r0), "=r"(r1), "=r"(r2), "=r"(r3) : "r"(addr));
}
__device__ __forceinline__ void mma16816(float d[4], const uint32_t a[4], const uint32_t b[2]) {
    asm volatile(
        "mma.sync.aligned.m16n8k16.row.col.f32.f16.f16.f32 "
        "{%0,%1,%2,%3}, {%4,%5,%6,%7}, {%8,%9}, {%0,%1,%2,%3};"
        : "+f"(d[0]), "+f"(d[1]), "+f"(d[2]), "+f"(d[3])
        : "r"(a[0]), "r"(a[1]), "r"(a[2]), "r"(a[3]), "r"(b[0]), "r"(b[1]));
}
__device__ __forceinline__ uint32_t pack_h2(float f0, float f1) {
    __half2 h = __floats2half2_rn(f0, f1);
    return *(const uint32_t*)&h;
}
__device__ __forceinline__ float2 unpack_h2(uint32_t u) {
    return __half22float2(*(const __half2*)&u);
}

// Warp-level fp16 GEMM via ldmatrix (verified R14)
template<int MT, int NT, int K16>
__device__ __forceinline__ void warp_mma_f16(
    float (&acc)[MT][NT][4],
    uint32_t sA, uint32_t sB, int m0, int n0, int lane)
{
    const uint32_t aOff = (uint32_t)((lane & 7) + ((lane >> 3) & 1) * 8) * ROWB
                        + (uint32_t)((lane >> 4) & 1) * 16;
    const uint32_t bOff = (uint32_t)((lane & 7) + ((lane >> 4) & 1) * 8) * ROWB
                        + (uint32_t)((lane >> 3) & 1) * 16;
#pragma unroll
    for (int ks = 0; ks < K16; ks++) {
        uint32_t af[MT][4];
#pragma unroll
        for (int mi = 0; mi < MT; mi++)
            ldsm_x4(af[mi][0], af[mi][1], af[mi][2], af[mi][3],
                    sA + (uint32_t)(m0 + mi * 16) * ROWB + (uint32_t)ks * 32 + aOff);
        uint32_t bf[NT][2];
#pragma unroll
        for (int nj = 0; nj < NT / 2; nj++)
            ldsm_x4(bf[2 * nj][0], bf[2 * nj][1], bf[2 * nj + 1][0], bf[2 * nj + 1][1],
                    sB + (uint32_t)(n0 + nj * 16) * ROWB + (uint32_t)ks * 32 + bOff);
#pragma unroll
        for (int ni = 0; ni < NT; ni++)
#pragma unroll
            for (int mi = 0; mi < MT; mi++)
                mma16816(acc[mi][ni], af[mi], bf[ni]);
    }
}

// ---------------------------------------------------------------------------
// k_prep: weight images + mask (mask folded into block 0)
// ---------------------------------------------------------------------------
__global__ void k_prep(const float* __restrict__ W1,
                       const float* __restrict__ W2,
                       const float* __restrict__ Wc,
                       const float* __restrict__ Wd,
                       const int* __restrict__ cm) {
    if (blockIdx.x == 0 && threadIdx.x < NA) {
        int i = threadIdx.x;
        int cnt = 0;
#pragma unroll
        for (int j = 0; j < NA; j++)
            cnt += (j != i && cm[i * NA + j] != 0) ? 1 : 0;
        float inv = 1.0f / (float)(cnt > 0 ? cnt : 1);
#pragma unroll
        for (int jp = 0; jp < 16; jp++) {
            float f0 = (2 * jp     != i && cm[i * NA + 2 * jp]     != 0) ? inv : 0.0f;
            float f1 = (2 * jp + 1 != i && cm[i * NA + 2 * jp + 1] != 0) ? inv : 0.0f;
            __half h0 = __float2half_rn(f0);
            __half h1 = __float2half_rn(f1);
            g_m16[i * 16 + jp] =
                ((uint32_t)__half_as_ushort(h1) << 16) | (uint32_t)__half_as_ushort(h0);
            g_m16[512 + i * 16 + jp] =
                pack_h2(f0 - __half2float(h0), f1 - __half2float(h1));
        }
    }
    const int T1 = NA * NH1 * 64;
    const int T2 = NA * NHX * 64;
    const int T4 = NA * NACT * 32;
    const int total = T1 + 2 * T2 + T4;
    for (int idx = blockIdx.x * blockDim.x + threadIdx.x; idx < total;
         idx += gridDim.x * blockDim.x) {
        const float* src; unsigned char* dst; int N, JP, K; int t;
        if (idx < T1)                { t = idx;                src = W1; dst = g_W1t; N = NH1;  JP = 64; K = 128; }
        else if (idx < T1 + T2)      { t = idx - T1;           src = W2; dst = g_W2t; N = NHX;  JP = 64; K = 128; }
        else if (idx < T1 + 2 * T2)  { t = idx - T1 - T2;      src = Wc; dst = g_Wct; N = NHX;  JP = 64; K = 128; }
        else                         { t = idx - T1 - 2 * T2;  src = Wd; dst = g_Wdt; N = NACT; JP = 32; K = 64;  }
        int perA = N * JP;
        int a = t / perA, r = t % perA;
        int n = r / JP,   j = r % JP;
        float f0 = src[((size_t)a * K + 2 * j)     * N + n];
        float f1 = src[((size_t)a * K + 2 * j + 1) * N + n];
        unsigned char* base = dst + (size_t)a * N * ROWB;
        *(uint32_t*)(base + (size_t)n * ROWB + j * 4) = pack_h2(f0, f1);
    }
}

// ---------------------------------------------------------------------------
// k_encode HYBRID: blocks x<SPLIT_E -> fp16 tensor path (128 rows);
//                  blocks x>=SPLIT_E -> fp32 FFMA path (64 rows, R1-verified)
// ---------------------------------------------------------------------------
#define E_A    0
#define E_W1   34816
#define E_W2   69632
#define E_B1   87040
#define E_B2   87552
// scalar overlay: Ws fp32 [0,65536) | aT [65536,98816) | bias [98816,99328)
#define E_SMEM 99328

__global__ __launch_bounds__(256) void k_encode(
    const float* __restrict__ obs,
    const float* __restrict__ b1, const float* __restrict__ b2,
    const float* __restrict__ W1f, const float* __restrict__ W2f)
{
    extern __shared__ unsigned char smraw[];
    const int tid  = threadIdx.x;
    const int a    = blockIdx.y;

    if (blockIdx.x < SPLIT_E) {
        // ===================== TENSOR PATH (verified R14) =====================
        const uint32_t sb = smem_u32(smraw);
        const int w    = tid >> 5;
        const int lane = tid & 31;
        const int b0   = blockIdx.x * 128;

        {
            const float4* s1 = (const float4*)(g_W1t + (size_t)a * 34816);
            float4* d1 = (float4*)(smraw + E_W1);
            for (int i = tid; i < 2176; i += 256) d1[i] = s1[i];
            const float4* s2 = (const float4*)(g_W2t + (size_t)a * 17408);
            float4* d2 = (float4*)(smraw + E_W2);
            for (int i = tid; i < 1088; i += 256) d2[i] = s2[i];
        }
        for (int i = tid; i < 128 * 32; i += 256) {
            int m = i >> 5, kq = i & 31;
            float4 v = *(const float4*)(obs + ((size_t)(b0 + m) * NA + a) * NOBS + kq * 4);
            sts_v2(sb + E_A + (uint32_t)m * ROWB + (uint32_t)kq * 8,
                   pack_h2(v.x, v.y), pack_h2(v.z, v.w));
        }
        if (tid < NH1) ((float*)(smraw + E_B1))[tid] = b1[a * NH1 + tid];
        if (tid < NHX) ((float*)(smraw + E_B2))[tid] = b2[a * NHX + tid];
        __syncthreads();

        {   // GEMM1: warp tile 64m x 32n
            const int m0 = (w & 1) * 64;
            const int n0 = (w >> 1) * 32;
            float acc[4][4][4];
#pragma unroll
            for (int mi = 0; mi < 4; mi++)
#pragma unroll
                for (int ni = 0; ni < 4; ni++)
#pragma unroll
                    for (int e = 0; e < 4; e++) acc[mi][ni][e] = 0.0f;

            warp_mma_f16<4, 4, 8>(acc, sb + E_A, sb + E_W1, m0, n0, lane);
            __syncthreads();

            const float* b1s = (const float*)(smraw + E_B1);
#pragma unroll
            for (int mi = 0; mi < 4; mi++)
#pragma unroll
                for (int ni = 0; ni < 4; ni++) {
                    int r = m0 + mi * 16 + (lane >> 2);
                    int c = n0 + ni * 8 + 2 * (lane & 3);
                    float bb0 = b1s[c], bb1 = b1s[c + 1];
                    uint32_t off = (uint32_t)r * ROWB + (uint32_t)c * 2;
                    sts_u32(sb + E_A + off,
                            pack_h2(fmaxf(acc[mi][ni][0] + bb0, 0.0f),
                                    fmaxf(acc[mi][ni][1] + bb1, 0.0f)));
                    sts_u32(sb + E_A + off + 8 * ROWB,
                            pack_h2(fmaxf(acc[mi][ni][2] + bb0, 0.0f),
                                    fmaxf(acc[mi][ni][3] + bb1, 0.0f)));
                }
        }
        __syncthreads();

        {   // GEMM2: warp tile 32m x 32n
            const int m0 = (w & 3) * 32;
            const int n0 = (w >> 2) * 32;
            float acc[2][4][4];
#pragma unroll
            for (int mi = 0; mi < 2; mi++)
#pragma unroll
                for (int ni = 0; ni < 4; ni++)
#pragma unroll
                    for (int e = 0; e < 4; e++) acc[mi][ni][e] = 0.0f;

            warp_mma_f16<2, 4, 8>(acc, sb + E_A, sb + E_W2, m0, n0, lane);

            const float* b2s = (const float*)(smraw + E_B2);
#pragma unroll
            for (int mi = 0; mi < 2; mi++)
#pragma unroll
                for (int ni = 0; ni < 4; ni++) {
                    int r = m0 + mi * 16 + (lane >> 2);
                    int c = n0 + ni * 8 + 2 * (lane & 3);
                    float bb0 = b2s[c], bb1 = b2s[c + 1];
                    g_h2[((size_t)(b0 + r) * NA + a) * 32 + (c >> 1)] =
                        pack_h2(fmaxf(acc[mi][ni][0] + bb0, 0.0f),
                                fmaxf(acc[mi][ni][1] + bb1, 0.0f));
                    g_h2[((size_t)(b0 + r + 8) * NA + a) * 32 + (c >> 1)] =
                        pack_h2(fmaxf(acc[mi][ni][2] + bb0, 0.0f),
                                fmaxf(acc[mi][ni][3] + bb1, 0.0f));
                }
        }
    } else {
        // ===================== SCALAR FFMA PATH (R1-verified) =================
        float* Ws   = (float*)smraw;                 // 128x128
        float* aT   = (float*)(smraw + 65536);       // 128 x PAD
        float* bias = (float*)(smraw + 98816);       // 128
        const int b0 = SPLIT_E * 128 + (blockIdx.x - SPLIT_E) * 64;

        {
            const float4* src = (const float4*)(W1f + (size_t)a * NOBS * NH1);
            float4* dst = (float4*)Ws;
            for (int i = tid; i < NOBS * NH1 / 4; i += 256) dst[i] = src[i];
        }
        for (int i = tid; i < 64 * NOBS / 4; i += 256) {
            int m = i >> 5, kq = i & 31;
            float4 v = *(const float4*)(obs + ((size_t)(b0 + m) * NA + a) * NOBS + kq * 4);
            int k = kq * 4;
            aT[(k + 0) * PAD + m] = v.x;  aT[(k + 1) * PAD + m] = v.y;
            aT[(k + 2) * PAD + m] = v.z;  aT[(k + 3) * PAD + m] = v.w;
        }
        if (tid < NH1) bias[tid] = b1[a * NH1 + tid];
        __syncthreads();

        const int tm = tid >> 5;    // warp id -> rows tm*8..+7 (broadcast A)
        const int tn = tid & 31;

        // GEMM1: acc[8][4], cols tn+32j
        float acc[8][4];
#pragma unroll
        for (int i = 0; i < 8; i++)
#pragma unroll
            for (int j = 0; j < 4; j++) acc[i][j] = 0.0f;
#pragma unroll 4
        for (int k = 0; k < NOBS; k++) {
            float av[8], bv[4];
#pragma unroll
            for (int i = 0; i < 8; i++) av[i] = aT[k * PAD + tm * 8 + i];
#pragma unroll
            for (int j = 0; j < 4; j++) bv[j] = Ws[k * NH1 + tn + j * 32];
#pragma unroll
            for (int i = 0; i < 8; i++)
#pragma unroll
                for (int j = 0; j < 4; j++) acc[i][j] += av[i] * bv[j];
        }
#pragma unroll
        for (int j = 0; j < 4; j++) {
            float bb = bias[tn + j * 32];
#pragma unroll
            for (int i = 0; i < 8; i++) acc[i][j] = fmaxf(acc[i][j] + bb, 0.0f);
        }
        __syncthreads();
#pragma unroll
        for (int j = 0; j < 4; j++)
#pragma unroll
            for (int i = 0; i < 8; i++)
                aT[(tn + j * 32) * PAD + tm * 8 + i] = acc[i][j];

        {
            const float4* src = (const float4*)(W2f + (size_t)a * NH1 * NHX);
            float4* dst = (float4*)Ws;
            for (int i = tid; i < NH1 * NHX / 4; i += 256) dst[i] = src[i];
        }
        if (tid < NHX) bias[tid] = b2[a * NHX + tid];
        __syncthreads();

        // GEMM2: cols 2tn, 2tn+1 (adjacent -> half2 pack)
        float a0 = 0.0f, a1 = 0.0f, acc2[8][2];
#pragma unroll
        for (int i = 0; i < 8; i++) { acc2[i][0] = 0.0f; acc2[i][1] = 0.0f; }
        (void)a0; (void)a1;
#pragma unroll 4
        for (int k = 0; k < NH1; k++) {
            float av[8];
#pragma unroll
            for (int i = 0; i < 8; i++) av[i] = aT[k * PAD + tm * 8 + i];
            float2 bv = *(float2*)&Ws[k * NHX + tn * 2];
#pragma unroll
            for (int i = 0; i < 8; i++) {
                acc2[i][0] += av[i] * bv.x;
                acc2[i][1] += av[i] * bv.y;
            }
        }
        float bb0 = bias[tn * 2], bb1 = bias[tn * 2 + 1];
#pragma unroll
        for (int i = 0; i < 8; i++) {
            int m = b0 + tm * 8 + i;
            g_h2[((size_t)m * NA + a) * 32 + tn] =
                pack_h2(fmaxf(acc2[i][0] + bb0, 0.0f), fmaxf(acc2[i][1] + bb1, 0.0f));
        }
    }
}

// ---------------------------------------------------------------------------
// k_comm via mma: comm[b] = (Mhi+Mlo) @ h[b] ; 8 batches/block, warp = 1 batch
// ---------------------------------------------------------------------------
#define CM_MROW 80
#define CM_HROW 144
#define C_MH    0
#define C_ML    2560
#define C_H     5120
#define C_SMEM  (5120 + 8 * 4608)

__global__ __launch_bounds__(256) void k_comm() {
    __shared__ __align__(16) unsigned char csm[C_SMEM];
    const uint32_t sb = smem_u32(csm);
    const int tid  = threadIdx.x;
    const int w    = tid >> 5;
    const int lane = tid & 31;
    const int bbase = blockIdx.x * 8;

    {
        const uint4* ms = (const uint4*)g_m16;
        uint4 v = ms[tid];
        int t = tid >> 7, row = (tid >> 2) & 31, q = tid & 3;
        *(uint4*)(csm + (t ? C_ML : C_MH) + row * CM_MROW + q * 16) = v;
    }
    {
        const uint4* hsrc = (const uint4*)g_h2;
        for (int i = tid; i < 2048; i += 256) {
            int r = i >> 8, j = (i >> 3) & 31, q = i & 7;
            uint4 v = hsrc[(((size_t)(bbase + r) * NA + j) << 3) + q];
            *(uint4*)(csm + C_H + r * 4608 + j * CM_HROW + q * 16) = v;
        }
    }
    __syncthreads();

    const int b = bbase + w;   // warp w -> batch

    uint32_t A[2][2][2][4];    // [term][mtile][kstep][4]
    const uint32_t aOffM = (uint32_t)((lane & 7) + ((lane >> 3) & 1) * 8) * CM_MROW
                         + (uint32_t)((lane >> 4) & 1) * 16;
#pragma unroll
    for (int t = 0; t < 2; t++)
#pragma unroll
        for (int mt = 0; mt < 2; mt++)
#pragma unroll
            for (int ks = 0; ks < 2; ks++)
                ldsm_x4(A[t][mt][ks][0], A[t][mt][ks][1], A[t][mt][ks][2], A[t][mt][ks][3],
                        sb + (t ? C_ML : C_MH) + (uint32_t)(mt * 16) * CM_MROW
                           + (uint32_t)ks * 32 + aOffM);

    float acc[2][8][4];
#pragma unroll
    for (int mt = 0; mt < 2; mt++)
#pragma unroll
        for (int nt = 0; nt < 8; nt++)
#pragma unroll
            for (int e = 0; e < 4; e++) acc[mt][nt][e] = 0.0f;

    const uint32_t hb = sb + C_H + w * 4608;
    const uint32_t bOffT = (uint32_t)((lane & 7) + ((lane >> 3) & 1) * 8) * CM_HROW
                         + (uint32_t)((lane >> 4) & 1) * 16;
#pragma unroll
    for (int nj = 0; nj < 4; nj++) {
#pragma unroll
        for (int ks = 0; ks < 2; ks++) {
            uint32_t q0, q1, q2, q3;
            ldsm_x4_t(q0, q1, q2, q3,
                      hb + (uint32_t)(ks * 16) * CM_HROW + (uint32_t)nj * 32 + bOffT);
            uint32_t bf0[2] = {q0, q1};
            uint32_t bf1[2] = {q2, q3};
#pragma unroll
            for (int t = 0; t < 2; t++)
#pragma unroll
                for (int mt = 0; mt < 2; mt++) {
                    mma16816(acc[mt][2 * nj],     A[t][mt][ks], bf0);
                    mma16816(acc[mt][2 * nj + 1], A[t][mt][ks], bf1);
                }
        }
    }

#pragma unroll
    for (int mt = 0; mt < 2; mt++)
#pragma unroll
        for (int nt = 0; nt < 8; nt++) {
            int i0 = mt * 16 + (lane >> 2);
            int n  = nt * 8 + 2 * (lane & 3);
            g_c2[((size_t)b * NA + i0) * 32 + (n >> 1)]     = pack_h2(acc[mt][nt][0], acc[mt][nt][1]);
            g_c2[((size_t)b * NA + i0 + 8) * 32 + (n >> 1)] = pack_h2(acc[mt][nt][2], acc[mt][nt][3]);
        }
}

// ---------------------------------------------------------------------------
// k_final HYBRID: x<SPLIT_E tensor (128 rows); else scalar fp32 (64 rows)
// ---------------------------------------------------------------------------
#define F_A    0
#define F_WC   34816
#define F_WDT  52224
#define F_BC   56576
#define F_BD   56832
// scalar overlay: Wc fp32 [0,32768) | aT [32768,66048) | Wd [66048,70144) | bc,bd
#define F_SMEM 70464

__global__ __launch_bounds__(256) void k_final(
    const float* __restrict__ bc, const float* __restrict__ bd,
    const float* __restrict__ Wcf, const float* __restrict__ Wdf,
    float* __restrict__ q)
{
    extern __shared__ unsigned char smraw[];
    const int tid  = threadIdx.x;
    const int a    = blockIdx.y;

    if (blockIdx.x < SPLIT_E) {
        // ===================== TENSOR PATH (verified R14) =====================
        const uint32_t sbm = smem_u32(smraw);
        const int w    = tid >> 5;
        const int lane = tid & 31;
        const int b0   = blockIdx.x * 128;

        {
            const float4* s3 = (const float4*)(g_Wct + (size_t)a * 17408);
            float4* d3 = (float4*)(smraw + F_WC);
            for (int i = tid; i < 1088; i += 256) d3[i] = s3[i];
            const float4* s4 = (const float4*)(g_Wdt + (size_t)a * 4352);
            float4* d4 = (float4*)(smraw + F_WDT);
            for (int i = tid; i < 272; i += 256) d4[i] = s4[i];
        }
        for (int i = tid; i < 128 * 64; i += 256) {
            int m = i >> 6, j = i & 63;
            uint32_t v = (j < 32)
                ? g_h2[((size_t)(b0 + m) * NA + a) * 32 + j]
                : g_c2[((size_t)(b0 + m) * NA + a) * 32 + (j - 32)];
            sts_u32(sbm + F_A + (uint32_t)m * ROWB + (uint32_t)j * 4, v);
        }
        if (tid < NHX)  ((float*)(smraw + F_BC))[tid] = bc[a * NHX + tid];
        if (tid < NACT) ((float*)(smraw + F_BD))[tid] = bd[a * NACT + tid];
        __syncthreads();

        {
            float acc[2][4][4];
#pragma unroll
            for (int mi = 0; mi < 2; mi++)
#pragma unroll
                for (int ni = 0; ni < 4; ni++)
#pragma unroll
                    for (int e = 0; e < 4; e++) acc[mi][ni][e] = 0.0f;

            const int m0 = (w & 3) * 32;
            const int n0 = (w >> 2) * 32;
            warp_mma_f16<2, 4, 8>(acc, sbm + F_A, sbm + F_WC, m0, n0, lane);
            __syncthreads();

            const float* bcs = (const float*)(smraw + F_BC);
#pragma unroll
            for (int mi = 0; mi < 2; mi++)
#pragma unroll
                for (int ni = 0; ni < 4; ni++) {
                    int r = m0 + mi * 16 + (lane >> 2);
                    int c = n0 + ni * 8 + 2 * (lane & 3);
                    float bb0 = bcs[c], bb1 = bcs[c + 1];
                    uint32_t off = (uint32_t)r * ROWB + (uint32_t)c * 2;
                    sts_u32(sbm + F_A + off,
                            pack_h2(tanhf(acc[mi][ni][0] + bb0), tanhf(acc[mi][ni][1] + bb1)));
                    sts_u32(sbm + F_A + off + 8 * ROWB,
                            pack_h2(tanhf(acc[mi][ni][2] + bb0), tanhf(acc[mi][ni][3] + bb1)));
                }
        }
        __syncthreads();

        {
            float acc[1][2][4];
#pragma unroll
            for (int ni = 0; ni < 2; ni++)
#pragma unroll
                for (int e = 0; e < 4; e++) acc[0][ni][e] = 0.0f;

            warp_mma_f16<1, 2, 4>(acc, sbm + F_A, sbm + F_WDT, w * 16, 0, lane);

            const float* bds = (const float*)(smraw + F_BD);
#pragma unroll
            for (int ni = 0; ni < 2; ni++) {
                int r = w * 16 + (lane >> 2);
                int c = ni * 8 + 2 * (lane & 3);
                float bb0 = bds[c], bb1 = bds[c + 1];
                *(float2*)(q + ((size_t)(b0 + r) * NA + a) * NACT + c) =
                    make_float2(acc[0][ni][0] + bb0, acc[0][ni][1] + bb1);
                *(float2*)(q + ((size_t)(b0 + r + 8) * NA + a) * NACT + c) =
                    make_float2(acc[0][ni][2] + bb0, acc[0][ni][3] + bb1);
            }
        }
    } else {
        // ===================== SCALAR FFMA PATH (R1-verified) =================
        float* Ws  = (float*)smraw;                  // Wc 128x64
        float* aT  = (float*)(smraw + 32768);        // 128 x PAD
        float* Wds = (float*)(smraw + 66048);        // 64x16
        float* bcs = (float*)(smraw + 70144);        // 64
        float* bds = bcs + NHX;                      // 16
        const int b0 = SPLIT_E * 128 + (blockIdx.x - SPLIT_E) * 64;

        {
            const float4* src = (const float4*)(Wcf + (size_t)a * 2 * NHX * NHX);
            float4* dst = (float4*)Ws;
            for (int i = tid; i < 2 * NHX * NHX / 4; i += 256) dst[i] = src[i];
            const float4* sw = (const float4*)(Wdf + (size_t)a * NHX * NACT);
            float4* dw = (float4*)Wds;
            for (int i = tid; i < 256; i += 256) dw[i] = sw[i];
        }
        // stage concat transposed (unpack fp16 -> fp32): k rows 0..127
        for (int i = tid; i < 64 * 64; i += 256) {
            int m = i >> 6, j = i & 63;
            uint32_t v = (j < 32)
                ? g_h2[((size_t)(b0 + m) * NA + a) * 32 + j]
                : g_c2[((size_t)(b0 + m) * NA + a) * 32 + (j - 32)];
            float2 f = unpack_h2(v);
            aT[(2 * j) * PAD + m]     = f.x;
            aT[(2 * j + 1) * PAD + m] = f.y;
        }
        if (tid < NHX)  bcs[tid] = bc[a * NHX + tid];
        if (tid < NACT) bds[tid] = bd[a * NACT + tid];
        __syncthreads();

        const int tm = tid >> 5;
        const int tn = tid & 31;

        // GEMM3: acc[8][2], cols 2tn, 2tn+1
        float acc[8][2];
#pragma unroll
        for (int i = 0; i < 8; i++) { acc[i][0] = 0.0f; acc[i][1] = 0.0f; }
#pragma unroll 4
        for (int k = 0; k < 2 * NHX; k++) {
            float av[8];
#pragma unroll
            for (int i = 0; i < 8; i++) av[i] = aT[k * PAD + tm * 8 + i];
            float2 bv = *(float2*)&Ws[k * NHX + tn * 2];
#pragma unroll
            for (int i = 0; i < 8; i++) {
                acc[i][0] += av[i] * bv.x;
                acc[i][1] += av[i] * bv.y;
            }
        }
        float bb0 = bcs[tn * 2], bb1 = bcs[tn * 2 + 1];
#pragma unroll
        for (int i = 0; i < 8; i++) {
            acc[i][0] = tanhf(acc[i][0] + bb0);
            acc[i][1] = tanhf(acc[i][1] + bb1);
        }
        __syncthreads();
#pragma unroll
        for (int i = 0; i < 8; i++) {
            aT[(tn * 2) * PAD + tm * 8 + i]     = acc[i][0];
            aT[(tn * 2 + 1) * PAD + tm * 8 + i] = acc[i][1];
        }
        __syncthreads();

        // GEMM4: m = tid&63, g = tid>>6
        const int m = tid & 63;
        const int g = tid >> 6;
        float acc3[4] = {bds[g * 4 + 0], bds[g * 4 + 1], bds[g * 4 + 2], bds[g * 4 + 3]};
#pragma unroll 8
        for (int k = 0; k < NHX; k++) {
            float av = aT[k * PAD + m];
#pragma unroll
            for (int jj = 0; jj < 4; jj++) acc3[jj] += av * Wds[k * NACT + g * 4 + jj];
        }
        *(float4*)(q + ((size_t)(b0 + m) * NA + a) * NACT + g * 4) =
            make_float4(acc3[0], acc3[1], acc3[2], acc3[3]);
    }
}

// ---------------------------------------------------------------------------
extern "C" void kernel_launch(void* const* d_in, const int* in_sizes, int n_in,
                              void* d_out, int out_size) {
    const float* obs = (const float*)d_in[0];
    const float* W1  = (const float*)d_in[1];
    const float* b1  = (const float*)d_in[2];
    const float* W2  = (const float*)d_in[3];
    const float* b2  = (const float*)d_in[4];
    // d_in[5], d_in[6]: Wg, bg — dead code (gates never reach the output)
    const float* Wc  = (const float*)d_in[7];
    const float* bc  = (const float*)d_in[8];
    const float* Wd  = (const float*)d_in[9];
    const float* bd  = (const float*)d_in[10];
    const int*   cm  = (const int*)d_in[11];
    float* q = (float*)d_out;

    cudaFuncSetAttribute(k_encode, cudaFuncAttributeMaxDynamicSharedMemorySize, E_SMEM);
    cudaFuncSetAttribute(k_final,  cudaFuncAttributeMaxDynamicSharedMemorySize, F_SMEM);

    k_prep<<<256, 256>>>(W1, W2, Wc, Wd, cm);
    k_encode<<<dim3(SPLIT_E + 32, NA), 256, E_SMEM>>>(obs, b1, b2, W1, W2);
    k_comm<<<NB / 8, 256>>>();
    k_final<<<dim3(SPLIT_E + 32, NA), 256, F_SMEM>>>(bc, bd, Wc, Wd, q);
}

// round 17
// speedup vs baseline: 1.5894x; 1.5894x over previous
#include <cuda_runtime.h>
#include <cuda_fp16.h>
#include <math.h>
#include <stdint.h>

#define NB   8192
#define NA   32
#define NOBS 128
#define NH1  128
#define NHX  64
#define NACT 16

#define ROWB   272          // fp16 padded row (136 halfs); ldsm conflict-free

// ---------------------------------------------------------------------------
// Scratch + prepped weight images (allocation-free rule: __device__ globals)
// ---------------------------------------------------------------------------
__device__ unsigned int g_h2[NB * NA * 32];      // h  activations, half2-packed
__device__ unsigned int g_c2[NB * NA * 32];      // comm, half2-packed
__device__ unsigned int g_m16[32 * 16];          // M fp16 image [i][jpair]
// Transposed fp16 weight images, pad-136 rows: image[n][k] = W[k][n]
__device__ unsigned char g_W1t[NA * NH1 * ROWB];
__device__ unsigned char g_W2t[NA * NHX * ROWB];
__device__ unsigned char g_Wct[NA * NHX * ROWB];
__device__ unsigned char g_Wdt[NA * NACT * ROWB];

// ---------------------------------------------------------------------------
// Helpers
// ---------------------------------------------------------------------------
__device__ __forceinline__ uint32_t smem_u32(const void* p) {
    uint32_t a;
    asm("{ .reg .u64 t; cvta.to.shared.u64 t, %1; cvt.u32.u64 %0, t; }"
        : "=r"(a) : "l"(p));
    return a;
}
__device__ __forceinline__ void sts_u32(uint32_t addr, uint32_t v) {
    asm volatile("st.shared.b32 [%0], %1;" :: "r"(addr), "r"(v));
}
__device__ __forceinline__ void sts_v2(uint32_t addr, uint32_t a, uint32_t b) {
    asm volatile("st.shared.v2.b32 [%0], {%1,%2};" :: "r"(addr), "r"(a), "r"(b));
}
__device__ __forceinline__ void ldsm_x4(uint32_t &r0, uint32_t &r1, uint32_t &r2,
                                        uint32_t &r3, uint32_t addr) {
    asm volatile("ldmatrix.sync.aligned.m8n8.x4.shared.b16 {%0,%1,%2,%3}, [%4];"
                 : "=r"(r0), "=r"(r1), "=r"(r2), "=r"(r3) : "r"(addr));
}
__device__ __forceinline__ void ldsm_x4_t(uint32_t &r0, uint32_t &r1, uint32_t &r2,
                                          uint32_t &r3, uint32_t addr) {
    asm volatile("ldmatrix.sync.aligned.m8n8.x4.trans.shared.b16 {%0,%1,%2,%3}, [%4];"
                 : "=r"(r0), "=r"(r1), "=r"(r2), "=r"(r3) : "r"(addr));
}
__device__ __forceinline__ void mma16816(float d[4], const uint32_t a[4], const uint32_t b[2]) {
    asm volatile(
        "mma.sync.aligned.m16n8k16.row.col.f32.f16.f16.f32 "
        "{%0,%1,%2,%3}, {%4,%5,%6,%7}, {%8,%9}, {%0,%1,%2,%3};"
        : "+f"(d[0]), "+f"(d[1]), "+f"(d[2]), "+f"(d[3])
        : "r"(a[0]), "r"(a[1]), "r"(a[2]), "r"(a[3]), "r"(b[0]), "r"(b[1]));
}
__device__ __forceinline__ uint32_t pack_h2(float f0, float f1) {
    __half2 h = __floats2half2_rn(f0, f1);
    return *(const uint32_t*)&h;
}

// Warp-level fp16 GEMM via ldmatrix (verified R14)
template<int MT, int NT, int K16>
__device__ __forceinline__ void warp_mma_f16(
    float (&acc)[MT][NT][4],
    uint32_t sA, uint32_t sB, int m0, int n0, int lane)
{
    const uint32_t aOff = (uint32_t)((lane & 7) + ((lane >> 3) & 1) * 8) * ROWB
                        + (uint32_t)((lane >> 4) & 1) * 16;
    const uint32_t bOff = (uint32_t)((lane & 7) + ((lane >> 4) & 1) * 8) * ROWB
                        + (uint32_t)((lane >> 3) & 1) * 16;
#pragma unroll
    for (int ks = 0; ks < K16; ks++) {
        uint32_t af[MT][4];
#pragma unroll
        for (int mi = 0; mi < MT; mi++)
            ldsm_x4(af[mi][0], af[mi][1], af[mi][2], af[mi][3],
                    sA + (uint32_t)(m0 + mi * 16) * ROWB + (uint32_t)ks * 32 + aOff);
        uint32_t bf[NT][2];
#pragma unroll
        for (int nj = 0; nj < NT / 2; nj++)
            ldsm_x4(bf[2 * nj][0], bf[2 * nj][1], bf[2 * nj + 1][0], bf[2 * nj + 1][1],
                    sB + (uint32_t)(n0 + nj * 16) * ROWB + (uint32_t)ks * 32 + bOff);
#pragma unroll
        for (int ni = 0; ni < NT; ni++)
#pragma unroll
            for (int mi = 0; mi < MT; mi++)
                mma16816(acc[mi][ni], af[mi], bf[ni]);
    }
}

// ---------------------------------------------------------------------------
// k_prep: weight images + mask (mask folded into block 0)
// ---------------------------------------------------------------------------
__global__ void k_prep(const float* __restrict__ W1,
                       const float* __restrict__ W2,
                       const float* __restrict__ Wc,
                       const float* __restrict__ Wd,
                       const int* __restrict__ cm) {
    if (blockIdx.x == 0 && threadIdx.x < NA) {
        int i = threadIdx.x;
        int cnt = 0;
#pragma unroll
        for (int j = 0; j < NA; j++)
            cnt += (j != i && cm[i * NA + j] != 0) ? 1 : 0;
        float inv = 1.0f / (float)(cnt > 0 ? cnt : 1);
#pragma unroll
        for (int jp = 0; jp < 16; jp++) {
            float f0 = (2 * jp     != i && cm[i * NA + 2 * jp]     != 0) ? inv : 0.0f;
            float f1 = (2 * jp + 1 != i && cm[i * NA + 2 * jp + 1] != 0) ? inv : 0.0f;
            g_m16[i * 16 + jp] = pack_h2(f0, f1);
        }
    }
    const int T1 = NA * NH1 * 64;
    const int T2 = NA * NHX * 64;
    const int T4 = NA * NACT * 32;
    const int total = T1 + 2 * T2 + T4;
    for (int idx = blockIdx.x * blockDim.x + threadIdx.x; idx < total;
         idx += gridDim.x * blockDim.x) {
        const float* src; unsigned char* dst; int N, JP, K; int t;
        if (idx < T1)                { t = idx;                src = W1; dst = g_W1t; N = NH1;  JP = 64; K = 128; }
        else if (idx < T1 + T2)      { t = idx - T1;           src = W2; dst = g_W2t; N = NHX;  JP = 64; K = 128; }
        else if (idx < T1 + 2 * T2)  { t = idx - T1 - T2;      src = Wc; dst = g_Wct; N = NHX;  JP = 64; K = 128; }
        else                         { t = idx - T1 - 2 * T2;  src = Wd; dst = g_Wdt; N = NACT; JP = 32; K = 64;  }
        int perA = N * JP;
        int a = t / perA, r = t % perA;
        int n = r / JP,   j = r % JP;
        float f0 = src[((size_t)a * K + 2 * j)     * N + n];
        float f1 = src[((size_t)a * K + 2 * j + 1) * N + n];
        unsigned char* base = dst + (size_t)a * N * ROWB;
        *(uint32_t*)(base + (size_t)n * ROWB + j * 4) = pack_h2(f0, f1);
    }
}

// ---------------------------------------------------------------------------
// k_encode: h = relu(relu(obs@W1+b1)@W2+b2), fp16 mma, M=128/block (R14-verified)
// ---------------------------------------------------------------------------
#define E_A    0
#define E_W1   34816
#define E_W2   69632
#define E_B1   87040
#define E_B2   87552
#define E_SMEM 87808

__global__ __launch_bounds__(256) void k_encode(
    const float* __restrict__ obs,
    const float* __restrict__ b1, const float* __restrict__ b2)
{
    extern __shared__ unsigned char smraw[];
    const uint32_t sb = smem_u32(smraw);
    const int tid  = threadIdx.x;
    const int w    = tid >> 5;
    const int lane = tid & 31;
    const int a    = blockIdx.y;
    const int b0   = blockIdx.x * 128;

    {
        const float4* s1 = (const float4*)(g_W1t + (size_t)a * 34816);
        float4* d1 = (float4*)(smraw + E_W1);
        for (int i = tid; i < 2176; i += 256) d1[i] = s1[i];
        const float4* s2 = (const float4*)(g_W2t + (size_t)a * 17408);
        float4* d2 = (float4*)(smraw + E_W2);
        for (int i = tid; i < 1088; i += 256) d2[i] = s2[i];
    }
    for (int i = tid; i < 128 * 32; i += 256) {
        int m = i >> 5, kq = i & 31;
        float4 v = *(const float4*)(obs + ((size_t)(b0 + m) * NA + a) * NOBS + kq * 4);
        sts_v2(sb + E_A + (uint32_t)m * ROWB + (uint32_t)kq * 8,
               pack_h2(v.x, v.y), pack_h2(v.z, v.w));
    }
    if (tid < NH1) ((float*)(smraw + E_B1))[tid] = b1[a * NH1 + tid];
    if (tid < NHX) ((float*)(smraw + E_B2))[tid] = b2[a * NHX + tid];
    __syncthreads();

    // GEMM1: x[128,128] ; warp tile 64m x 32n
    {
        const int m0 = (w & 1) * 64;
        const int n0 = (w >> 1) * 32;
        float acc[4][4][4];
#pragma unroll
        for (int mi = 0; mi < 4; mi++)
#pragma unroll
            for (int ni = 0; ni < 4; ni++)
#pragma unroll
                for (int e = 0; e < 4; e++) acc[mi][ni][e] = 0.0f;

        warp_mma_f16<4, 4, 8>(acc, sb + E_A, sb + E_W1, m0, n0, lane);
        __syncthreads();

        const float* b1s = (const float*)(smraw + E_B1);
#pragma unroll
        for (int mi = 0; mi < 4; mi++)
#pragma unroll
            for (int ni = 0; ni < 4; ni++) {
                int r = m0 + mi * 16 + (lane >> 2);
                int c = n0 + ni * 8 + 2 * (lane & 3);
                float bb0 = b1s[c], bb1 = b1s[c + 1];
                uint32_t off = (uint32_t)r * ROWB + (uint32_t)c * 2;
                sts_u32(sb + E_A + off,
                        pack_h2(fmaxf(acc[mi][ni][0] + bb0, 0.0f),
                                fmaxf(acc[mi][ni][1] + bb1, 0.0f)));
                sts_u32(sb + E_A + off + 8 * ROWB,
                        pack_h2(fmaxf(acc[mi][ni][2] + bb0, 0.0f),
                                fmaxf(acc[mi][ni][3] + bb1, 0.0f)));
            }
    }
    __syncthreads();

    // GEMM2: h[128,64] ; warp tile 32m x 32n
    {
        const int m0 = (w & 3) * 32;
        const int n0 = (w >> 2) * 32;
        float acc[2][4][4];
#pragma unroll
        for (int mi = 0; mi < 2; mi++)
#pragma unroll
            for (int ni = 0; ni < 4; ni++)
#pragma unroll
                for (int e = 0; e < 4; e++) acc[mi][ni][e] = 0.0f;

        warp_mma_f16<2, 4, 8>(acc, sb + E_A, sb + E_W2, m0, n0, lane);

        const float* b2s = (const float*)(smraw + E_B2);
#pragma unroll
        for (int mi = 0; mi < 2; mi++)
#pragma unroll
            for (int ni = 0; ni < 4; ni++) {
                int r = m0 + mi * 16 + (lane >> 2);
                int c = n0 + ni * 8 + 2 * (lane & 3);
                float bb0 = b2s[c], bb1 = b2s[c + 1];
                g_h2[((size_t)(b0 + r) * NA + a) * 32 + (c >> 1)] =
                    pack_h2(fmaxf(acc[mi][ni][0] + bb0, 0.0f),
                            fmaxf(acc[mi][ni][1] + bb1, 0.0f));
                g_h2[((size_t)(b0 + r + 8) * NA + a) * 32 + (c >> 1)] =
                    pack_h2(fmaxf(acc[mi][ni][2] + bb0, 0.0f),
                            fmaxf(acc[mi][ni][3] + bb1, 0.0f));
            }
    }
}

// ---------------------------------------------------------------------------
// k_comm via mma: comm[b] = M @ h[b] ; single fp16 term; 8 batches/block
// ---------------------------------------------------------------------------
#define CM_MROW 80
#define CM_HROW 144
#define C_MH    0
#define C_H     2560
#define C_SMEM  (2560 + 8 * 4608)   // 39424

__global__ __launch_bounds__(256) void k_comm() {
    __shared__ __align__(16) unsigned char csm[C_SMEM];
    const uint32_t sb = smem_u32(csm);
    const int tid  = threadIdx.x;
    const int w    = tid >> 5;
    const int lane = tid & 31;
    const int bbase = blockIdx.x * 8;

    // Stage M image (rows stride 80B): 128 uint4
    if (tid < 128) {
        uint4 v = ((const uint4*)g_m16)[tid];
        int row = tid >> 2, qd = tid & 3;
        *(uint4*)(csm + C_MH + row * CM_MROW + qd * 16) = v;
    }
    // Stage h rows for 8 batches (rows stride 144B)
    {
        const uint4* hsrc = (const uint4*)g_h2;
        for (int i = tid; i < 2048; i += 256) {
            int r = i >> 8, j = (i >> 3) & 31, qd = i & 7;
            uint4 v = hsrc[(((size_t)(bbase + r) * NA + j) << 3) + qd];
            *(uint4*)(csm + C_H + r * 4608 + j * CM_HROW + qd * 16) = v;
        }
    }
    __syncthreads();

    const int b = bbase + w;   // warp w -> batch

    uint32_t A[2][2][4];       // [mtile][kstep][4]
    const uint32_t aOffM = (uint32_t)((lane & 7) + ((lane >> 3) & 1) * 8) * CM_MROW
                         + (uint32_t)((lane >> 4) & 1) * 16;
#pragma unroll
    for (int mt = 0; mt < 2; mt++)
#pragma unroll
        for (int ks = 0; ks < 2; ks++)
            ldsm_x4(A[mt][ks][0], A[mt][ks][1], A[mt][ks][2], A[mt][ks][3],
                    sb + C_MH + (uint32_t)(mt * 16) * CM_MROW
                       + (uint32_t)ks * 32 + aOffM);

    float acc[2][8][4];
#pragma unroll
    for (int mt = 0; mt < 2; mt++)
#pragma unroll
        for (int nt = 0; nt < 8; nt++)
#pragma unroll
            for (int e = 0; e < 4; e++) acc[mt][nt][e] = 0.0f;

    const uint32_t hb = sb + C_H + w * 4608;
    const uint32_t bOffT = (uint32_t)((lane & 7) + ((lane >> 3) & 1) * 8) * CM_HROW
                         + (uint32_t)((lane >> 4) & 1) * 16;
#pragma unroll
    for (int nj = 0; nj < 4; nj++) {
#pragma unroll
        for (int ks = 0; ks < 2; ks++) {
            uint32_t q0, q1, q2, q3;
            ldsm_x4_t(q0, q1, q2, q3,
                      hb + (uint32_t)(ks * 16) * CM_HROW + (uint32_t)nj * 32 + bOffT);
            uint32_t bf0[2] = {q0, q1};
            uint32_t bf1[2] = {q2, q3};
#pragma unroll
            for (int mt = 0; mt < 2; mt++) {
                mma16816(acc[mt][2 * nj],     A[mt][ks], bf0);
                mma16816(acc[mt][2 * nj + 1], A[mt][ks], bf1);
            }
        }
    }

#pragma unroll
    for (int mt = 0; mt < 2; mt++)
#pragma unroll
        for (int nt = 0; nt < 8; nt++) {
            int i0 = mt * 16 + (lane >> 2);
            int n  = nt * 8 + 2 * (lane & 3);
            g_c2[((size_t)b * NA + i0) * 32 + (n >> 1)]     = pack_h2(acc[mt][nt][0], acc[mt][nt][1]);
            g_c2[((size_t)b * NA + i0 + 8) * 32 + (n >> 1)] = pack_h2(acc[mt][nt][2], acc[mt][nt][3]);
        }
}

// ---------------------------------------------------------------------------
// k_final: h2 = tanh([h,comm]@Wc + bc); q = h2@Wd + bd (R14-verified)
// ---------------------------------------------------------------------------
#define F_A    0
#define F_WC   34816
#define F_WDT  52224
#define F_BC   56576
#define F_BD   56832
#define F_SMEM 56896

__global__ __launch_bounds__(256) void k_final(
    const float* __restrict__ bc, const float* __restrict__ bd,
    float* __restrict__ q)
{
    extern __shared__ unsigned char smraw[];
    const uint32_t sbm = smem_u32(smraw);
    const int tid  = threadIdx.x;
    const int w    = tid >> 5;
    const int lane = tid & 31;
    const int a    = blockIdx.y;
    const int b0   = blockIdx.x * 128;

    {
        const float4* s3 = (const float4*)(g_Wct + (size_t)a * 17408);
        float4* d3 = (float4*)(smraw + F_WC);
        for (int i = tid; i < 1088; i += 256) d3[i] = s3[i];
        const float4* s4 = (const float4*)(g_Wdt + (size_t)a * 4352);
        float4* d4 = (float4*)(smraw + F_WDT);
        for (int i = tid; i < 272; i += 256) d4[i] = s4[i];
    }
    for (int i = tid; i < 128 * 64; i += 256) {
        int m = i >> 6, j = i & 63;
        uint32_t v = (j < 32)
            ? g_h2[((size_t)(b0 + m) * NA + a) * 32 + j]
            : g_c2[((size_t)(b0 + m) * NA + a) * 32 + (j - 32)];
        sts_u32(sbm + F_A + (uint32_t)m * ROWB + (uint32_t)j * 4, v);
    }
    if (tid < NHX)  ((float*)(smraw + F_BC))[tid] = bc[a * NHX + tid];
    if (tid < NACT) ((float*)(smraw + F_BD))[tid] = bd[a * NACT + tid];
    __syncthreads();

    // GEMM3: pre[128,64] ; warp tile 32m x 32n
    {
        float acc[2][4][4];
#pragma unroll
        for (int mi = 0; mi < 2; mi++)
#pragma unroll
            for (int ni = 0; ni < 4; ni++)
#pragma unroll
                for (int e = 0; e < 4; e++) acc[mi][ni][e] = 0.0f;

        const int m0 = (w & 3) * 32;
        const int n0 = (w >> 2) * 32;
        warp_mma_f16<2, 4, 8>(acc, sbm + F_A, sbm + F_WC, m0, n0, lane);
        __syncthreads();

        const float* bcs = (const float*)(smraw + F_BC);
#pragma unroll
        for (int mi = 0; mi < 2; mi++)
#pragma unroll
            for (int ni = 0; ni < 4; ni++) {
                int r = m0 + mi * 16 + (lane >> 2);
                int c = n0 + ni * 8 + 2 * (lane & 3);
                float bb0 = bcs[c], bb1 = bcs[c + 1];
                uint32_t off = (uint32_t)r * ROWB + (uint32_t)c * 2;
                sts_u32(sbm + F_A + off,
                        pack_h2(tanhf(acc[mi][ni][0] + bb0), tanhf(acc[mi][ni][1] + bb1)));
                sts_u32(sbm + F_A + off + 8 * ROWB,
                        pack_h2(tanhf(acc[mi][ni][2] + bb0), tanhf(acc[mi][ni][3] + bb1)));
            }
    }
    __syncthreads();

    // GEMM4: q[128,16] ; warp w -> rows w*16..w*16+15, K=64
    {
        float acc[1][2][4];
#pragma unroll
        for (int ni = 0; ni < 2; ni++)
#pragma unroll
            for (int e = 0; e < 4; e++) acc[0][ni][e] = 0.0f;

        warp_mma_f16<1, 2, 4>(acc, sbm + F_A, sbm + F_WDT, w * 16, 0, lane);

        const float* bds = (const float*)(smraw + F_BD);
#pragma unroll
        for (int ni = 0; ni < 2; ni++) {
            int r = w * 16 + (lane >> 2);
            int c = ni * 8 + 2 * (lane & 3);
            float bb0 = bds[c], bb1 = bds[c + 1];
            *(float2*)(q + ((size_t)(b0 + r) * NA + a) * NACT + c) =
                make_float2(acc[0][ni][0] + bb0, acc[0][ni][1] + bb1);
            *(float2*)(q + ((size_t)(b0 + r + 8) * NA + a) * NACT + c) =
                make_float2(acc[0][ni][2] + bb0, acc[0][ni][3] + bb1);
        }
    }
}

// ---------------------------------------------------------------------------
extern "C" void kernel_launch(void* const* d_in, const int* in_sizes, int n_in,
                              void* d_out, int out_size) {
    const float* obs = (const float*)d_in[0];
    const float* W1  = (const float*)d_in[1];
    const float* b1  = (const float*)d_in[2];
    const float* W2  = (const float*)d_in[3];
    const float* b2  = (const float*)d_in[4];
    // d_in[5], d_in[6]: Wg, bg — dead code (gates never reach the output)
    const float* Wc  = (const float*)d_in[7];
    const float* bc  = (const float*)d_in[8];
    const float* Wd  = (const float*)d_in[9];
    const float* bd  = (const float*)d_in[10];
    const int*   cm  = (const int*)d_in[11];
    float* q = (float*)d_out;

    cudaFuncSetAttribute(k_encode, cudaFuncAttributeMaxDynamicSharedMemorySize, E_SMEM);
    cudaFuncSetAttribute(k_final,  cudaFuncAttributeMaxDynamicSharedMemorySize, F_SMEM);

    k_prep<<<256, 256>>>(W1, W2, Wc, Wd, cm);
    k_encode<<<dim3(NB / 128, NA), 256, E_SMEM>>>(obs, b1, b2);
    k_comm<<<NB / 8, 256>>>();
    k_final<<<dim3(NB / 128, NA), 256, F_SMEM>>>(bc, bd, q);
}